// round 11
// baseline (speedup 1.0000x reference)
#include <cuda_runtime.h>
#include <cuda_fp16.h>
#include <cstdint>

#define KDIM 4096
#define BK 64
#define NKB (KDIM / BK)        // 64
#define A_BYTES 8192           // 64 rows x 128B
#define B_BYTES 16384          // 128 rows x 128B
#define STG_BYTES (A_BYTES + B_BYTES)   // 24576
#define SMEM_BYTES (4 * STG_BYTES)      // 98304

// ---- scratch: fp16 copies (static device arrays; no runtime alloc) ----
__device__ __half g_xh[512 * 4096];          // A[m][k]
__device__ __half g_wh[4096ull * 4096];      // B[n][k]

// ============ merged converter (coalesced) ============
// blocks [0,2048): w[i,j,p,q] -> wh[n=i*8+q][kk=j*8+p], 128B loads + stores
// blocks [2048,2560): x -> xh, 4 float4s per thread
__global__ void cvt_kernel(const float* __restrict__ x, const float* __restrict__ w) {
    const int b = blockIdx.x;
    const int t = threadIdx.x;
    if (b < 2048) {
        const int i  = b >> 2;                 // out octonion
        const int jl = t >> 1;                 // 0..127
        const int q4 = t & 1;                  // q-quad: q = 4*q4+d
        const int j  = (b & 3) * 128 + jl;
        const float* src = w + (size_t)i * 32768 + j * 64 + q4 * 4;
        float4 f[8];
        #pragma unroll
        for (int p = 0; p < 8; ++p)
            f[p] = *reinterpret_cast<const float4*>(src + p * 8);
        #pragma unroll
        for (int d = 0; d < 4; ++d) {
            __half h[8];
            h[0] = __float2half_rn((&f[0].x)[d]);
            h[1] = __float2half_rn((&f[1].x)[d]);
            h[2] = __float2half_rn((&f[2].x)[d]);
            h[3] = __float2half_rn((&f[3].x)[d]);
            h[4] = __float2half_rn((&f[4].x)[d]);
            h[5] = __float2half_rn((&f[5].x)[d]);
            h[6] = __float2half_rn((&f[6].x)[d]);
            h[7] = __float2half_rn((&f[7].x)[d]);
            const int n = i * 8 + q4 * 4 + d;
            *reinterpret_cast<uint4*>(g_wh + (size_t)n * 4096 + j * 8) =
                *reinterpret_cast<uint4*>(h);
        }
    } else {
        const int base = (b - 2048) * 1024 + t;        // float4 index
        __half2* dst = reinterpret_cast<__half2*>(g_xh);
        #pragma unroll
        for (int s = 0; s < 4; ++s) {
            const int i = base + s * 256;
            const float4 v = reinterpret_cast<const float4*>(x)[i];
            dst[2 * i]     = __floats2half2_rn(v.x, v.y);
            dst[2 * i + 1] = __floats2half2_rn(v.z, v.w);
        }
    }
}

// ============ GEMM ============
__device__ __forceinline__ uint32_t smem_u32(const void* p) {
    uint32_t a;
    asm("{ .reg .u64 t; cvta.to.shared.u64 t, %1; cvt.u32.u64 %0, t; }" : "=r"(a) : "l"(p));
    return a;
}
__device__ __forceinline__ void cp16(uint32_t dst, const void* src) {
    asm volatile("cp.async.cg.shared.global [%0], [%1], 16;" :: "r"(dst), "l"(src));
}
__device__ __forceinline__ void ldsm_x4(uint32_t* r, uint32_t addr) {
    asm volatile("ldmatrix.sync.aligned.m8n8.x4.shared.b16 {%0,%1,%2,%3}, [%4];"
                 : "=r"(r[0]), "=r"(r[1]), "=r"(r[2]), "=r"(r[3]) : "r"(addr));
}
__device__ __forceinline__ void mma_f16(float* d, const uint32_t* a, const uint32_t* b) {
    asm volatile(
        "mma.sync.aligned.m16n8k16.row.col.f32.f16.f16.f32 "
        "{%0,%1,%2,%3}, {%4,%5,%6,%7}, {%8,%9}, {%0,%1,%2,%3};"
        : "+f"(d[0]), "+f"(d[1]), "+f"(d[2]), "+f"(d[3])
        : "r"(a[0]), "r"(a[1]), "r"(a[2]), "r"(a[3]),
          "r"(b[0]), "r"(b[1]));
}

__global__ __launch_bounds__(256, 2)
void octonion_gemm_f16(const float* __restrict__ bias, float* __restrict__ out)
{
    extern __shared__ char smem[];
    const uint32_t sbase = smem_u32(smem);

    const int tid  = threadIdx.x;
    const int lane = tid & 31;
    const int warp = tid >> 5;
    const int wm   = warp >> 2;          // 0..1 -> 32-row strip
    const int wn   = warp & 3;           // 0..3 -> 32-col strip
    const int row0 = blockIdx.y * 64;
    const int col0 = blockIdx.x * 128;

    // ---- loader: 2 A + 4 B 16B chunks per thread per stage ----
    const int lr = tid >> 3;             // 0..31
    const int lu = tid & 7;
    const __half* aSrc = g_xh + (size_t)(row0 + lr) * KDIM + lu * 8;
    const __half* bSrc = g_wh + (size_t)(col0 + lr) * KDIM + lu * 8;
    uint32_t dstOff[4];
    #pragma unroll
    for (int i = 0; i < 4; ++i) {
        const int r = lr + 32 * i;
        dstOff[i] = (uint32_t)((r & 63) * 128 + (((uint32_t)lu ^ (r & 7)) << 4));
    }

    // ---- precomputed fragment addressing ----
    // swizzled unit is identical for all mt/ntp since row strides are mult of 8
    const int ubit = lane >> 4;
    uint32_t swx[4];
    #pragma unroll
    for (int ks = 0; ks < 4; ++ks)
        swx[ks] = (uint32_t)(((2 * ks + ubit) ^ (lane & 7)) << 4);
    const uint32_t aBase = (uint32_t)((wm * 32 + (lane & 15)) * 128);
    const uint32_t bBase = A_BYTES + (uint32_t)((wn * 32 + (lane & 15)) * 128);

    float acc[2][4][4];
    #pragma unroll
    for (int i = 0; i < 2; ++i)
        #pragma unroll
        for (int j = 0; j < 4; ++j)
            #pragma unroll
            for (int r = 0; r < 4; ++r)
                acc[i][j][r] = 0.0f;

    // ---- prologue: 3 stages in flight ----
    #pragma unroll
    for (int s = 0; s < 3; ++s) {
        const uint32_t so = sbase + s * STG_BYTES;
        #pragma unroll
        for (int i = 0; i < 2; ++i)
            cp16(so + dstOff[i], aSrc + (size_t)(s * BK) + (size_t)(32 * i) * KDIM);
        #pragma unroll
        for (int i = 0; i < 4; ++i)
            cp16(so + A_BYTES + dstOff[i] + (uint32_t)(i >> 1) * 8192,
                 bSrc + (size_t)(s * BK) + (size_t)(32 * i) * KDIM);
        asm volatile("cp.async.commit_group;" ::: "memory");
    }

    uint32_t a[2][2][4], bf[2][4][2];

    for (int kb = 0; kb < NKB; ++kb) {
        asm volatile("cp.async.wait_group 2;" ::: "memory");
        __syncthreads();

        // issue next stage's loads first (slot (kb+3)&3 was consumed at kb-1)
        if (kb + 3 < NKB) {
            const uint32_t sn = sbase + ((kb + 3) & 3) * STG_BYTES;
            const size_t ko = (size_t)(kb + 3) * BK;
            #pragma unroll
            for (int i = 0; i < 2; ++i)
                cp16(sn + dstOff[i], aSrc + ko + (size_t)(32 * i) * KDIM);
            #pragma unroll
            for (int i = 0; i < 4; ++i)
                cp16(sn + A_BYTES + dstOff[i] + (uint32_t)(i >> 1) * 8192,
                     bSrc + ko + (size_t)(32 * i) * KDIM);
            asm volatile("cp.async.commit_group;" ::: "memory");
        }

        const uint32_t so = sbase + (kb & 3) * STG_BYTES;

        // load ks=0 fragments
        #pragma unroll
        for (int mt = 0; mt < 2; ++mt)
            ldsm_x4(a[0][mt], so + aBase + mt * 2048u + swx[0]);
        #pragma unroll
        for (int ntp = 0; ntp < 2; ++ntp) {
            uint32_t t4[4];
            ldsm_x4(t4, so + bBase + ntp * 2048u + swx[0]);
            bf[0][2 * ntp][0] = t4[0]; bf[0][2 * ntp + 1][0] = t4[1];
            bf[0][2 * ntp][1] = t4[2]; bf[0][2 * ntp + 1][1] = t4[3];
        }

        #pragma unroll
        for (int ks = 0; ks < 4; ++ks) {
            const int cur = ks & 1, nxt = cur ^ 1;
            if (ks < 3) {
                #pragma unroll
                for (int mt = 0; mt < 2; ++mt)
                    ldsm_x4(a[nxt][mt], so + aBase + mt * 2048u + swx[ks + 1]);
                #pragma unroll
                for (int ntp = 0; ntp < 2; ++ntp) {
                    uint32_t t4[4];
                    ldsm_x4(t4, so + bBase + ntp * 2048u + swx[ks + 1]);
                    bf[nxt][2 * ntp][0] = t4[0]; bf[nxt][2 * ntp + 1][0] = t4[1];
                    bf[nxt][2 * ntp][1] = t4[2]; bf[nxt][2 * ntp + 1][1] = t4[3];
                }
            }
            #pragma unroll
            for (int mt = 0; mt < 2; ++mt)
                #pragma unroll
                for (int nt = 0; nt < 4; ++nt)
                    mma_f16(acc[mt][nt], a[cur][mt], bf[cur][nt]);
        }
    }

    // ---- epilogue: + bias, float2 stores ----
    #pragma unroll
    for (int mt = 0; mt < 2; ++mt) {
        const int row = row0 + wm * 32 + mt * 16 + (lane >> 2);
        #pragma unroll
        for (int nt = 0; nt < 4; ++nt) {
            const int col = col0 + wn * 32 + nt * 8 + (lane & 3) * 2;
            const float2 bb = *reinterpret_cast<const float2*>(bias + col);
            float2 o0, o1;
            o0.x = acc[mt][nt][0] + bb.x;
            o0.y = acc[mt][nt][1] + bb.y;
            o1.x = acc[mt][nt][2] + bb.x;
            o1.y = acc[mt][nt][3] + bb.y;
            *reinterpret_cast<float2*>(out + (size_t)row * KDIM + col) = o0;
            *reinterpret_cast<float2*>(out + (size_t)(row + 8) * KDIM + col) = o1;
        }
    }
}

extern "C" void kernel_launch(void* const* d_in, const int* in_sizes, int n_in,
                              void* d_out, int out_size)
{
    const float* x    = (const float*)d_in[0];   // [512, 4096]
    const float* w    = (const float*)d_in[1];   // [512, 512, 8, 8]
    const float* bias = (const float*)d_in[2];   // [512, 8] -> flat [4096]
    float* out = (float*)d_out;                  // [512, 4096]

    cvt_kernel<<<2560, 256>>>(x, w);

    cudaFuncSetAttribute(octonion_gemm_f16,
                         cudaFuncAttributeMaxDynamicSharedMemorySize, SMEM_BYTES);
    dim3 grid(KDIM / 128, 512 / 64);             // (32, 8) = 256 CTAs
    octonion_gemm_f16<<<grid, 256, SMEM_BYTES>>>(bias, out);
}

// round 12
// speedup vs baseline: 1.0633x; 1.0633x over previous
#include <cuda_runtime.h>
#include <cuda_fp16.h>
#include <cstdint>

#define KDIM 4096
#define BK 64
#define NKB (KDIM / BK)        // 64
#define A_BYTES 8192           // 64 rows x 128B
#define B_BYTES 16384          // 128 rows x 128B
#define STG_BYTES (A_BYTES + B_BYTES)   // 24576
#define SMEM_BYTES (4 * STG_BYTES)      // 98304

// ---- scratch: fp16 copies (static device arrays; no runtime alloc) ----
__device__ __half g_xh[512 * 4096];          // A[m][k]
__device__ __half g_wh[4096ull * 4096];      // B[n][k]

// ============ merged converter (coalesced) ============
__global__ void cvt_kernel(const float* __restrict__ x, const float* __restrict__ w) {
    const int b = blockIdx.x;
    const int t = threadIdx.x;
    if (b < 2048) {
        const int i  = b >> 2;                 // out octonion
        const int jl = t >> 1;                 // 0..127
        const int q4 = t & 1;                  // q-quad: q = 4*q4+d
        const int j  = (b & 3) * 128 + jl;
        const float* src = w + (size_t)i * 32768 + j * 64 + q4 * 4;
        float4 f[8];
        #pragma unroll
        for (int p = 0; p < 8; ++p)
            f[p] = *reinterpret_cast<const float4*>(src + p * 8);
        #pragma unroll
        for (int d = 0; d < 4; ++d) {
            __half h[8];
            #pragma unroll
            for (int p = 0; p < 8; ++p)
                h[p] = __float2half_rn((&f[p].x)[d]);
            const int n = i * 8 + q4 * 4 + d;
            *reinterpret_cast<uint4*>(g_wh + (size_t)n * 4096 + j * 8) =
                *reinterpret_cast<uint4*>(h);
        }
    } else {
        const int base = (b - 2048) * 1024 + t;        // float4 index
        __half2* dst = reinterpret_cast<__half2*>(g_xh);
        #pragma unroll
        for (int s = 0; s < 4; ++s) {
            const int i = base + s * 256;
            const float4 v = reinterpret_cast<const float4*>(x)[i];
            dst[2 * i]     = __floats2half2_rn(v.x, v.y);
            dst[2 * i + 1] = __floats2half2_rn(v.z, v.w);
        }
    }
}

// ============ GEMM ============
__device__ __forceinline__ uint32_t smem_u32(const void* p) {
    uint32_t a;
    asm("{ .reg .u64 t; cvta.to.shared.u64 t, %1; cvt.u32.u64 %0, t; }" : "=r"(a) : "l"(p));
    return a;
}
__device__ __forceinline__ void cp16(uint32_t dst, const void* src) {
    asm volatile("cp.async.cg.shared.global [%0], [%1], 16;" :: "r"(dst), "l"(src));
}
__device__ __forceinline__ void ldsm_x4(uint32_t* r, uint32_t addr) {
    asm volatile("ldmatrix.sync.aligned.m8n8.x4.shared.b16 {%0,%1,%2,%3}, [%4];"
                 : "=r"(r[0]), "=r"(r[1]), "=r"(r[2]), "=r"(r[3]) : "r"(addr));
}
__device__ __forceinline__ void mma_f16(float* d, const uint32_t* a, const uint32_t* b) {
    asm volatile(
        "mma.sync.aligned.m16n8k16.row.col.f32.f16.f16.f32 "
        "{%0,%1,%2,%3}, {%4,%5,%6,%7}, {%8,%9}, {%0,%1,%2,%3};"
        : "+f"(d[0]), "+f"(d[1]), "+f"(d[2]), "+f"(d[3])
        : "r"(a[0]), "r"(a[1]), "r"(a[2]), "r"(a[3]),
          "r"(b[0]), "r"(b[1]));
}

// CTA 64x128, 128 threads, 4 warps each owning a 64x32 output strip.
__global__ __launch_bounds__(128, 2)
void octonion_gemm_f16(const float* __restrict__ bias, float* __restrict__ out)
{
    extern __shared__ char smem[];
    const uint32_t sbase = smem_u32(smem);

    const int tid  = threadIdx.x;
    const int lane = tid & 31;
    const int wn   = tid >> 5;           // warp 0..3 -> 32-col strip
    const int row0 = blockIdx.y * 64;
    const int col0 = blockIdx.x * 128;

    // ---- loader: 4 A + 8 B 16B chunks per thread per stage ----
    const int lr = tid >> 3;             // 0..15
    const int lu = tid & 7;
    const __half* aSrc = g_xh + (size_t)(row0 + lr) * KDIM + lu * 8;
    const __half* bSrc = g_wh + (size_t)(col0 + lr) * KDIM + lu * 8;
    uint32_t dOff[8];
    #pragma unroll
    for (int i = 0; i < 8; ++i) {
        const int r = lr + 16 * i;
        dOff[i] = (uint32_t)((r & 63) * 128 + (((uint32_t)lu ^ (r & 7)) << 4));
    }

    // ---- fragment addressing (swizzle unit identical across 16-row tiles) ----
    const int ubit = lane >> 4;
    uint32_t swx[4];
    #pragma unroll
    for (int ks = 0; ks < 4; ++ks)
        swx[ks] = (uint32_t)(((2 * ks + ubit) ^ (lane & 7)) << 4);
    const uint32_t aBase = (uint32_t)((lane & 15) * 128);
    const uint32_t bBase = A_BYTES + (uint32_t)((wn * 32 + (lane & 15)) * 128);

    float acc[4][4][4];
    #pragma unroll
    for (int i = 0; i < 4; ++i)
        #pragma unroll
        for (int j = 0; j < 4; ++j)
            #pragma unroll
            for (int r = 0; r < 4; ++r)
                acc[i][j][r] = 0.0f;

    // ---- prologue: 3 stages in flight ----
    #pragma unroll
    for (int s = 0; s < 3; ++s) {
        const uint32_t so = sbase + s * STG_BYTES;
        #pragma unroll
        for (int i = 0; i < 4; ++i)
            cp16(so + dOff[i], aSrc + (size_t)(s * BK) + (size_t)(16 * i) * KDIM);
        #pragma unroll
        for (int i = 0; i < 8; ++i)
            cp16(so + A_BYTES + dOff[i] + (uint32_t)(i >> 2) * 8192,
                 bSrc + (size_t)(s * BK) + (size_t)(16 * i) * KDIM);
        asm volatile("cp.async.commit_group;" ::: "memory");
    }

    for (int kb = 0; kb < NKB; ++kb) {
        asm volatile("cp.async.wait_group 2;" ::: "memory");
        __syncthreads();

        const uint32_t so = sbase + (kb & 3) * STG_BYTES;

        #pragma unroll
        for (int ks = 0; ks < 4; ++ks) {
            uint32_t a[4][4], b[4][2];
            #pragma unroll
            for (int mt = 0; mt < 4; ++mt)
                ldsm_x4(a[mt], so + aBase + mt * 2048u + swx[ks]);
            #pragma unroll
            for (int ntp = 0; ntp < 2; ++ntp) {
                uint32_t t4[4];
                ldsm_x4(t4, so + bBase + ntp * 2048u + swx[ks]);
                b[2 * ntp][0] = t4[0]; b[2 * ntp + 1][0] = t4[1];
                b[2 * ntp][1] = t4[2]; b[2 * ntp + 1][1] = t4[3];
            }
            #pragma unroll
            for (int mt = 0; mt < 4; ++mt)
                #pragma unroll
                for (int nt = 0; nt < 4; ++nt)
                    mma_f16(acc[mt][nt], a[mt], b[nt]);
        }

        if (kb + 3 < NKB) {
            const uint32_t sn = sbase + ((kb + 3) & 3) * STG_BYTES;
            const size_t ko = (size_t)(kb + 3) * BK;
            #pragma unroll
            for (int i = 0; i < 4; ++i)
                cp16(sn + dOff[i], aSrc + ko + (size_t)(16 * i) * KDIM);
            #pragma unroll
            for (int i = 0; i < 8; ++i)
                cp16(sn + A_BYTES + dOff[i] + (uint32_t)(i >> 2) * 8192,
                     bSrc + ko + (size_t)(16 * i) * KDIM);
            asm volatile("cp.async.commit_group;" ::: "memory");
        }
    }

    // ---- epilogue: + bias, float2 stores ----
    #pragma unroll
    for (int mt = 0; mt < 4; ++mt) {
        const int row = row0 + mt * 16 + (lane >> 2);
        #pragma unroll
        for (int nt = 0; nt < 4; ++nt) {
            const int col = col0 + wn * 32 + nt * 8 + (lane & 3) * 2;
            const float2 bb = *reinterpret_cast<const float2*>(bias + col);
            float2 o0, o1;
            o0.x = acc[mt][nt][0] + bb.x;
            o0.y = acc[mt][nt][1] + bb.y;
            o1.x = acc[mt][nt][2] + bb.x;
            o1.y = acc[mt][nt][3] + bb.y;
            *reinterpret_cast<float2*>(out + (size_t)row * KDIM + col) = o0;
            *reinterpret_cast<float2*>(out + (size_t)(row + 8) * KDIM + col) = o1;
        }
    }
}

extern "C" void kernel_launch(void* const* d_in, const int* in_sizes, int n_in,
                              void* d_out, int out_size)
{
    const float* x    = (const float*)d_in[0];   // [512, 4096]
    const float* w    = (const float*)d_in[1];   // [512, 512, 8, 8]
    const float* bias = (const float*)d_in[2];   // [512, 8] -> flat [4096]
    float* out = (float*)d_out;                  // [512, 4096]

    cvt_kernel<<<2560, 256>>>(x, w);

    cudaFuncSetAttribute(octonion_gemm_f16,
                         cudaFuncAttributeMaxDynamicSharedMemorySize, SMEM_BYTES);
    dim3 grid(KDIM / 128, 512 / 64);             // (32, 8) = 256 CTAs
    octonion_gemm_f16<<<grid, 128, SMEM_BYTES>>>(bias, out);
}